// round 1
// baseline (speedup 1.0000x reference)
#include <cuda_runtime.h>
#include <math_constants.h>

// Problem constants
#define Bb 2
#define Ss 2048
#define Dd 1024
#define Hh 16
#define HD 64
#define Mtot (Bb*Ss)   // 4096 rows

// Scratch (allocation-free rule: __device__ globals)
__device__ float g_Q [Mtot*Dd];
__device__ float g_K [Mtot*Dd];
__device__ float g_V [Mtot*Dd];
__device__ float g_AO[Mtot*Dd];

// ---------------------------------------------------------------------------
// SGEMM  C[M,N] = A[M,K] * W[N,K]^T (+bias)   — NT, both operands K-contiguous
// 128x128 block tile, BK=8, 256 threads, 8x8 microtile (2x2 strips of 4)
// ---------------------------------------------------------------------------
#define BM 128
#define BN 128
#define BK 8

template<bool HAS_BIAS>
__device__ __forceinline__ void sgemm_nt_body(
    const float* __restrict__ A,
    const float* __restrict__ W,
    const float* __restrict__ bias,
    float* __restrict__ C,
    int M, int N, int K)
{
    __shared__ float As[BK][BM];
    __shared__ float Bs[BK][BN];

    const int tid = threadIdx.x;
    const int tx  = tid & 15;
    const int ty  = tid >> 4;
    const int m0  = blockIdx.y * BM;
    const int n0  = blockIdx.x * BN;

    const int lr = tid >> 1;         // 0..127: row within tile
    const int lk = (tid & 1) << 2;   // 0 or 4: k offset (float4)

    const float* Aptr = A + (size_t)(m0 + lr) * K + lk;
    const float* Wptr = W + (size_t)(n0 + lr) * K + lk;

    float4 pa = *(const float4*)Aptr;
    float4 pb = *(const float4*)Wptr;

    float acc[8][8];
    #pragma unroll
    for (int i = 0; i < 8; i++)
        #pragma unroll
        for (int j = 0; j < 8; j++) acc[i][j] = 0.f;

    for (int kt = 0; kt < K; kt += BK) {
        As[lk+0][lr] = pa.x; As[lk+1][lr] = pa.y;
        As[lk+2][lr] = pa.z; As[lk+3][lr] = pa.w;
        Bs[lk+0][lr] = pb.x; Bs[lk+1][lr] = pb.y;
        Bs[lk+2][lr] = pb.z; Bs[lk+3][lr] = pb.w;
        __syncthreads();

        if (kt + BK < K) {               // prefetch next k-tile during compute
            pa = *(const float4*)(Aptr + kt + BK);
            pb = *(const float4*)(Wptr + kt + BK);
        }

        #pragma unroll
        for (int kk = 0; kk < BK; kk++) {
            float4 a0 = *(const float4*)&As[kk][ty*4];
            float4 a1 = *(const float4*)&As[kk][64 + ty*4];
            float4 b0 = *(const float4*)&Bs[kk][tx*4];
            float4 b1 = *(const float4*)&Bs[kk][64 + tx*4];
            float ar[8] = {a0.x,a0.y,a0.z,a0.w, a1.x,a1.y,a1.z,a1.w};
            float br[8] = {b0.x,b0.y,b0.z,b0.w, b1.x,b1.y,b1.z,b1.w};
            #pragma unroll
            for (int i = 0; i < 8; i++)
                #pragma unroll
                for (int j = 0; j < 8; j++)
                    acc[i][j] += ar[i] * br[j];
        }
        __syncthreads();
    }

    // Epilogue: rows {ty*4+i, 64+ty*4+i}, cols {tx*4+j, 64+tx*4+j}
    #pragma unroll
    for (int i = 0; i < 8; i++) {
        int m = m0 + ((i < 4) ? (ty*4 + i) : (64 + ty*4 + (i-4)));
        #pragma unroll
        for (int half = 0; half < 2; half++) {
            int n = n0 + ((half == 0) ? (tx*4) : (64 + tx*4));
            float4 v = make_float4(acc[i][half*4+0], acc[i][half*4+1],
                                   acc[i][half*4+2], acc[i][half*4+3]);
            if (HAS_BIAS) {
                v.x += bias[n+0]; v.y += bias[n+1];
                v.z += bias[n+2]; v.w += bias[n+3];
            }
            *(float4*)(C + (size_t)m * N + n) = v;
        }
    }
}

__global__ __launch_bounds__(256)
void sgemm_qkv(const float* __restrict__ x,
               const float* __restrict__ Wq,
               const float* __restrict__ Wk,
               const float* __restrict__ Wv)
{
    const float* W;
    float* C;
    if (blockIdx.z == 0)      { W = Wq; C = g_Q; }
    else if (blockIdx.z == 1) { W = Wk; C = g_K; }
    else                      { W = Wv; C = g_V; }
    sgemm_nt_body<false>(x, W, nullptr, C, Mtot, Dd, Dd);
}

__global__ __launch_bounds__(256)
void sgemm_out(const float* __restrict__ Wo,
               const float* __restrict__ bo,
               float* __restrict__ out)
{
    sgemm_nt_body<true>(g_AO, Wo, bo, out, Mtot, Dd, Dd);
}

// ---------------------------------------------------------------------------
// Flash attention: 1 thread = 1 query row (q, o accumulators in registers),
// KV chunks of 32 rows staged in smem, all K/V smem reads warp-broadcast.
// Block = 128 threads = 128 query rows of one (b,h). Grid = (S/128, B*H).
// ---------------------------------------------------------------------------
#define CH 32

__global__ __launch_bounds__(128)
void attn_kernel()
{
    __shared__ float4 Ks[CH * 16];   // [32 rows][64 floats]
    __shared__ float4 Vs[CH * 16];

    const int tid = threadIdx.x;
    const int row = blockIdx.x * 128 + tid;
    const int b   = blockIdx.y >> 4;    // / Hh
    const int h   = blockIdx.y & 15;    // % Hh

    const float* qp = g_Q + ((size_t)(b * Ss + row)) * Dd + h * HD;
    float4 q[16];
    #pragma unroll
    for (int i = 0; i < 16; i++) q[i] = *(const float4*)(qp + i*4);

    float4 o[16];
    #pragma unroll
    for (int i = 0; i < 16; i++) o[i] = make_float4(0.f,0.f,0.f,0.f);
    float mprev = -CUDART_INF_F;
    float l = 0.f;

    const float* Kbase = g_K + ((size_t)(b * Ss)) * Dd + h * HD;
    const float* Vbase = g_V + ((size_t)(b * Ss)) * Dd + h * HD;

    const float scale = 0.125f;   // 1/sqrt(64)

    for (int kc = 0; kc < Ss; kc += CH) {
        // cooperative tile load: 32 rows x 16 float4 per matrix, coalesced
        #pragma unroll
        for (int i = 0; i < 4; i++) {
            int idx = tid + i * 128;     // 0..511
            int r = idx >> 4;            // 0..31
            int c = idx & 15;            // 0..15
            Ks[idx] = *(const float4*)(Kbase + (size_t)(kc + r) * Dd + c*4);
            Vs[idx] = *(const float4*)(Vbase + (size_t)(kc + r) * Dd + c*4);
        }
        __syncthreads();

        // scores for this chunk (scaled)
        float s[CH];
        #pragma unroll
        for (int j = 0; j < CH; j++) {
            float ax = 0.f, ay = 0.f, az = 0.f, aw = 0.f;
            #pragma unroll
            for (int d = 0; d < 16; d++) {
                float4 k4 = Ks[j*16 + d];
                ax += q[d].x * k4.x;
                ay += q[d].y * k4.y;
                az += q[d].z * k4.z;
                aw += q[d].w * k4.w;
            }
            s[j] = ((ax + ay) + (az + aw)) * scale;
        }

        // online softmax update
        float mc = s[0];
        #pragma unroll
        for (int j = 1; j < CH; j++) mc = fmaxf(mc, s[j]);
        float mnew = fmaxf(mprev, mc);
        float corr = __expf(mprev - mnew);   // 0 on first chunk (exp(-inf))
        l *= corr;
        #pragma unroll
        for (int i = 0; i < 16; i++) {
            o[i].x *= corr; o[i].y *= corr; o[i].z *= corr; o[i].w *= corr;
        }

        #pragma unroll
        for (int j = 0; j < CH; j++) {
            float p = __expf(s[j] - mnew);
            l += p;
            #pragma unroll
            for (int d = 0; d < 16; d++) {
                float4 v = Vs[j*16 + d];
                o[d].x += p * v.x;
                o[d].y += p * v.y;
                o[d].z += p * v.z;
                o[d].w += p * v.w;
            }
        }
        mprev = mnew;
        __syncthreads();
    }

    const float inv = 1.f / l;
    float* op = g_AO + ((size_t)(b * Ss + row)) * Dd + h * HD;
    #pragma unroll
    for (int i = 0; i < 16; i++) {
        float4 r = o[i];
        r.x *= inv; r.y *= inv; r.z *= inv; r.w *= inv;
        *(float4*)(op + i*4) = r;
    }
}

// ---------------------------------------------------------------------------
extern "C" void kernel_launch(void* const* d_in, const int* in_sizes, int n_in,
                              void* d_out, int out_size)
{
    const float* x  = (const float*)d_in[0];
    const float* Wq = (const float*)d_in[1];
    const float* Wk = (const float*)d_in[2];
    const float* Wv = (const float*)d_in[3];
    const float* Wo = (const float*)d_in[4];
    const float* bo = (const float*)d_in[5];
    float* out = (float*)d_out;

    dim3 gqkv(Dd / BN, Mtot / BM, 3);
    sgemm_qkv<<<gqkv, 256>>>(x, Wq, Wk, Wv);

    dim3 gattn(Ss / 128, Bb * Hh);
    attn_kernel<<<gattn, 128>>>();

    dim3 gout(Dd / BN, Mtot / BM, 1);
    sgemm_out<<<gout, 256>>>(Wo, bo, out);
}

// round 3
// speedup vs baseline: 1.2472x; 1.2472x over previous
#include <cuda_runtime.h>
#include <cuda_bf16.h>
#include <math_constants.h>
#include <cstdint>

// Problem constants
#define Bb 2
#define Ss 2048
#define Dd 1024
#define Hh 16
#define HD 64
#define Mtot (Bb*Ss)   // 4096 rows

// ---------------------------------------------------------------------------
// Scratch (__device__ globals; allocation-free rule)
// ---------------------------------------------------------------------------
__device__ float g_Q [Mtot*Dd];
__device__ float g_K [Mtot*Dd];
__device__ float g_V [Mtot*Dd];
__device__ float g_AO[Mtot*Dd];

__device__ __nv_bfloat16 g_xh [Mtot*Dd], g_xl [Mtot*Dd];
__device__ __nv_bfloat16 g_wqh[Dd*Dd],   g_wql[Dd*Dd];
__device__ __nv_bfloat16 g_wkh[Dd*Dd],   g_wkl[Dd*Dd];
__device__ __nv_bfloat16 g_wvh[Dd*Dd],   g_wvl[Dd*Dd];
__device__ __nv_bfloat16 g_woh[Dd*Dd],   g_wol[Dd*Dd];
__device__ __nv_bfloat16 g_aoh[Mtot*Dd], g_aol[Mtot*Dd];

// ---------------------------------------------------------------------------
// PTX helpers (compute_103-safe only: ldmatrix / mma.sync / cp.async)
// ---------------------------------------------------------------------------
__device__ __forceinline__ uint32_t smem_u32(const void* p) {
    uint32_t a;
    asm("{ .reg .u64 t; cvta.to.shared.u64 t, %1; cvt.u32.u64 %0, t; }"
        : "=r"(a) : "l"(p));
    return a;
}

__device__ __forceinline__ void ldm_x4(uint32_t& r0, uint32_t& r1,
                                       uint32_t& r2, uint32_t& r3, uint32_t addr) {
    asm volatile("ldmatrix.sync.aligned.m8n8.x4.shared.b16 {%0,%1,%2,%3}, [%4];"
                 : "=r"(r0), "=r"(r1), "=r"(r2), "=r"(r3) : "r"(addr));
}

__device__ __forceinline__ void mma16816(float* c, const uint32_t* a, const uint32_t* b) {
    asm volatile(
        "mma.sync.aligned.m16n8k16.row.col.f32.bf16.bf16.f32 "
        "{%0,%1,%2,%3}, {%4,%5,%6,%7}, {%8,%9}, {%0,%1,%2,%3};"
        : "+f"(c[0]), "+f"(c[1]), "+f"(c[2]), "+f"(c[3])
        : "r"(a[0]), "r"(a[1]), "r"(a[2]), "r"(a[3]), "r"(b[0]), "r"(b[1]));
}

#define CP_ASYNC16(dst, src) \
    asm volatile("cp.async.cg.shared.global [%0], [%1], 16;" :: "r"(dst), "l"(src))
#define CP_COMMIT() asm volatile("cp.async.commit_group;" ::: "memory")
#define CP_WAIT(n)  asm volatile("cp.async.wait_group %0;" :: "n"(n) : "memory")

// ---------------------------------------------------------------------------
// fp32 -> bf16 hi/lo split (error-corrected GEMM inputs)
// ---------------------------------------------------------------------------
__global__ __launch_bounds__(256)
void split_bf16(const float* __restrict__ src,
                __nv_bfloat16* __restrict__ hi,
                __nv_bfloat16* __restrict__ lo, int n)
{
    int i = (blockIdx.x * 256 + threadIdx.x) * 4;
    if (i >= n) return;
    float4 v = *(const float4*)(src + i);
    __nv_bfloat16 ha = __float2bfloat16(v.x);
    __nv_bfloat16 hb = __float2bfloat16(v.y);
    __nv_bfloat16 hc = __float2bfloat16(v.z);
    __nv_bfloat16 hd = __float2bfloat16(v.w);
    __nv_bfloat16 la = __float2bfloat16(v.x - __bfloat162float(ha));
    __nv_bfloat16 lb = __float2bfloat16(v.y - __bfloat162float(hb));
    __nv_bfloat16 lc = __float2bfloat16(v.z - __bfloat162float(hc));
    __nv_bfloat16 ld = __float2bfloat16(v.w - __bfloat162float(hd));
    *(__nv_bfloat162*)(hi + i)     = __halves2bfloat162(ha, hb);
    *(__nv_bfloat162*)(hi + i + 2) = __halves2bfloat162(hc, hd);
    *(__nv_bfloat162*)(lo + i)     = __halves2bfloat162(la, lb);
    *(__nv_bfloat162*)(lo + i + 2) = __halves2bfloat162(lc, ld);
}

// ---------------------------------------------------------------------------
// HMMA bf16x3 GEMM:  C[M,N] = (Ah+Al)[M,K] @ (Bh+Bl)[N,K]^T (+bias)
// Tile 128x128x32, 256 threads (8 warps, 2x4), warp tile 64x32,
// double-buffered cp.async, ldmatrix from swizzled smem.
// Error-corrected: hi*hi + lo*hi + hi*lo into one fp32 accumulator.
// ---------------------------------------------------------------------------
#define GM 128
#define GN 128
#define GKC 32
#define NCHUNK (Dd / GKC)        // 32
#define TILEB (128 * GKC * 2)    // 8192 bytes per bf16 tile (128 rows x 64B)
#define STAGEB (4 * TILEB)       // AH, AL, BH, BL = 32KB
#define GEMM_SMEM (2 * STAGEB)   // 64KB

// swizzled smem address: row-major [128][32] bf16, 64B rows, 16B units,
// unit ^= (row>>1)&3  → conflict-free ldmatrix phases
__device__ __forceinline__ uint32_t sw_addr(uint32_t base, int row, int unit) {
    return base + row * 64 + ((unit ^ ((row >> 1) & 3)) << 4);
}

// async-copy one 128x32 bf16 tile (gmem stride Dd) into swizzled smem
__device__ __forceinline__ void cp_tile(uint32_t sdst, const __nv_bfloat16* __restrict__ g,
                                        int tid)
{
    #pragma unroll
    for (int i = 0; i < 2; i++) {
        int u   = tid + i * 256;     // 0..511
        int row = u >> 2;
        int cu  = u & 3;
        uint32_t dst = sw_addr(sdst, row, cu);
        const void* src = g + (size_t)row * Dd + cu * 8;
        CP_ASYNC16(dst, src);
    }
}

template<bool HAS_BIAS>
__device__ __forceinline__ void gemm_tc_body(
    const __nv_bfloat16* __restrict__ Ah, const __nv_bfloat16* __restrict__ Al,
    const __nv_bfloat16* __restrict__ Bh, const __nv_bfloat16* __restrict__ Bl,
    const float* __restrict__ bias, float* __restrict__ C)
{
    extern __shared__ char smem[];
    const uint32_t sb = smem_u32(smem);
    const int tid = threadIdx.x;
    const int wid = tid >> 5;
    const int lid = tid & 31;
    const int wm  = wid >> 2;        // 0..1
    const int wn  = wid & 3;         // 0..3
    const int m0  = blockIdx.y * GM;
    const int n0  = blockIdx.x * GN;

    const __nv_bfloat16* gAh = Ah + (size_t)m0 * Dd;
    const __nv_bfloat16* gAl = Al + (size_t)m0 * Dd;
    const __nv_bfloat16* gBh = Bh + (size_t)n0 * Dd;
    const __nv_bfloat16* gBl = Bl + (size_t)n0 * Dd;

    float acc[4][4][4];
    #pragma unroll
    for (int i = 0; i < 4; i++)
        #pragma unroll
        for (int j = 0; j < 4; j++)
            #pragma unroll
            for (int k = 0; k < 4; k++) acc[i][j][k] = 0.f;

    // ldmatrix lane roles (fixed per thread)
    const int a_row = wm * 64 + (lid & 15);          // + mt*16
    const int a_ku  = lid >> 4;                      // 0/1 within k16
    const int b_row = wn * 32 + (lid & 7) + ((lid >> 4) << 3);  // + pair*16
    const int b_ku  = (lid >> 3) & 1;

    // prologue: stage 0 <- chunk 0
    {
        uint32_t s = sb;
        cp_tile(s,             gAh, tid);
        cp_tile(s + TILEB,     gAl, tid);
        cp_tile(s + 2*TILEB,   gBh, tid);
        cp_tile(s + 3*TILEB,   gBl, tid);
        CP_COMMIT();
    }

    for (int c = 0; c < NCHUNK; c++) {
        if (c + 1 < NCHUNK) {
            uint32_t s = sb + ((c + 1) & 1) * STAGEB;
            const int kc = (c + 1) * GKC;
            cp_tile(s,           gAh + kc, tid);
            cp_tile(s + TILEB,   gAl + kc, tid);
            cp_tile(s + 2*TILEB, gBh + kc, tid);
            cp_tile(s + 3*TILEB, gBl + kc, tid);
            CP_COMMIT();
            CP_WAIT(1);
        } else {
            CP_WAIT(0);
        }
        __syncthreads();

        const uint32_t sa_h = sb + (c & 1) * STAGEB;
        const uint32_t sa_l = sa_h + TILEB;
        const uint32_t sbh  = sa_h + 2*TILEB;
        const uint32_t sbl  = sa_h + 3*TILEB;

        #pragma unroll
        for (int ks = 0; ks < 2; ks++) {
            const int ku = ks * 2;
            uint32_t bh[8], bl[8];
            #pragma unroll
            for (int pr = 0; pr < 2; pr++) {
                ldm_x4(bh[pr*4+0], bh[pr*4+1], bh[pr*4+2], bh[pr*4+3],
                       sw_addr(sbh, b_row + pr*16, ku + b_ku));
                ldm_x4(bl[pr*4+0], bl[pr*4+1], bl[pr*4+2], bl[pr*4+3],
                       sw_addr(sbl, b_row + pr*16, ku + b_ku));
            }
            #pragma unroll
            for (int mt = 0; mt < 4; mt++) {
                uint32_t ah[4], al[4];
                ldm_x4(ah[0], ah[1], ah[2], ah[3],
                       sw_addr(sa_h, a_row + mt*16, ku + a_ku));
                ldm_x4(al[0], al[1], al[2], al[3],
                       sw_addr(sa_l, a_row + mt*16, ku + a_ku));
                #pragma unroll
                for (int nt = 0; nt < 4; nt++) {
                    mma16816(acc[mt][nt], ah, &bh[nt*2]);
                    mma16816(acc[mt][nt], al, &bh[nt*2]);
                    mma16816(acc[mt][nt], ah, &bl[nt*2]);
                }
            }
        }
        __syncthreads();
    }

    // epilogue: fragment (t/4, (t%4)*2) rows +0/+8
    #pragma unroll
    for (int mt = 0; mt < 4; mt++) {
        const int row = m0 + wm*64 + mt*16 + (lid >> 2);
        #pragma unroll
        for (int nt = 0; nt < 4; nt++) {
            const int col = n0 + wn*32 + nt*8 + (lid & 3)*2;
            float2 v0 = make_float2(acc[mt][nt][0], acc[mt][nt][1]);
            float2 v1 = make_float2(acc[mt][nt][2], acc[mt][nt][3]);
            if (HAS_BIAS) {
                float2 bv = *(const float2*)(bias + col);
                v0.x += bv.x; v0.y += bv.y;
                v1.x += bv.x; v1.y += bv.y;
            }
            *(float2*)(C + (size_t)row * Dd + col)       = v0;
            *(float2*)(C + (size_t)(row + 8) * Dd + col) = v1;
        }
    }
}

__global__ __launch_bounds__(256)
void gemm_qkv_tc(const __nv_bfloat16* xh, const __nv_bfloat16* xl,
                 const __nv_bfloat16* qh, const __nv_bfloat16* ql,
                 const __nv_bfloat16* kh, const __nv_bfloat16* kl,
                 const __nv_bfloat16* vh, const __nv_bfloat16* vl,
                 float* Q, float* Kp, float* Vp)
{
    const __nv_bfloat16 *Bh, *Bl; float* C;
    if (blockIdx.z == 0)      { Bh = qh; Bl = ql; C = Q;  }
    else if (blockIdx.z == 1) { Bh = kh; Bl = kl; C = Kp; }
    else                      { Bh = vh; Bl = vl; C = Vp; }
    gemm_tc_body<false>(xh, xl, Bh, Bl, nullptr, C);
}

__global__ __launch_bounds__(256)
void gemm_o_tc(const __nv_bfloat16* ah, const __nv_bfloat16* al,
               const __nv_bfloat16* wh, const __nv_bfloat16* wl,
               const float* bias, float* out)
{
    gemm_tc_body<true>(ah, al, wh, wl, bias, out);
}

// ---------------------------------------------------------------------------
// Flash attention (scalar roofline, unchanged): 1 thread = 1 query row.
// ---------------------------------------------------------------------------
#define CH 32

__global__ __launch_bounds__(128)
void attn_kernel()
{
    __shared__ float4 Ks[CH * 16];
    __shared__ float4 Vs[CH * 16];

    const int tid = threadIdx.x;
    const int row = blockIdx.x * 128 + tid;
    const int b   = blockIdx.y >> 4;
    const int h   = blockIdx.y & 15;

    const float* qp = g_Q + ((size_t)(b * Ss + row)) * Dd + h * HD;
    float4 q[16];
    #pragma unroll
    for (int i = 0; i < 16; i++) q[i] = *(const float4*)(qp + i*4);

    float4 o[16];
    #pragma unroll
    for (int i = 0; i < 16; i++) o[i] = make_float4(0.f,0.f,0.f,0.f);
    float mprev = -CUDART_INF_F;
    float l = 0.f;

    const float* Kbase = g_K + ((size_t)(b * Ss)) * Dd + h * HD;
    const float* Vbase = g_V + ((size_t)(b * Ss)) * Dd + h * HD;
    const float scale = 0.125f;

    for (int kc = 0; kc < Ss; kc += CH) {
        #pragma unroll
        for (int i = 0; i < 4; i++) {
            int idx = tid + i * 128;
            int r = idx >> 4;
            int c = idx & 15;
            Ks[idx] = *(const float4*)(Kbase + (size_t)(kc + r) * Dd + c*4);
            Vs[idx] = *(const float4*)(Vbase + (size_t)(kc + r) * Dd + c*4);
        }
        __syncthreads();

        float s[CH];
        #pragma unroll
        for (int j = 0; j < CH; j++) {
            float ax = 0.f, ay = 0.f, az = 0.f, aw = 0.f;
            #pragma unroll
            for (int d = 0; d < 16; d++) {
                float4 k4 = Ks[j*16 + d];
                ax += q[d].x * k4.x;
                ay += q[d].y * k4.y;
                az += q[d].z * k4.z;
                aw += q[d].w * k4.w;
            }
            s[j] = ((ax + ay) + (az + aw)) * scale;
        }

        float mc = s[0];
        #pragma unroll
        for (int j = 1; j < CH; j++) mc = fmaxf(mc, s[j]);
        float mnew = fmaxf(mprev, mc);
        float corr = __expf(mprev - mnew);
        l *= corr;
        #pragma unroll
        for (int i = 0; i < 16; i++) {
            o[i].x *= corr; o[i].y *= corr; o[i].z *= corr; o[i].w *= corr;
        }

        #pragma unroll
        for (int j = 0; j < CH; j++) {
            float p = __expf(s[j] - mnew);
            l += p;
            #pragma unroll
            for (int d = 0; d < 16; d++) {
                float4 v = Vs[j*16 + d];
                o[d].x += p * v.x;
                o[d].y += p * v.y;
                o[d].z += p * v.z;
                o[d].w += p * v.w;
            }
        }
        mprev = mnew;
        __syncthreads();
    }

    const float inv = 1.f / l;
    float* op = g_AO + ((size_t)(b * Ss + row)) * Dd + h * HD;
    #pragma unroll
    for (int i = 0; i < 16; i++) {
        float4 r = o[i];
        r.x *= inv; r.y *= inv; r.z *= inv; r.w *= inv;
        *(float4*)(op + i*4) = r;
    }
}

// ---------------------------------------------------------------------------
extern "C" void kernel_launch(void* const* d_in, const int* in_sizes, int n_in,
                              void* d_out, int out_size)
{
    const float* x  = (const float*)d_in[0];
    const float* Wq = (const float*)d_in[1];
    const float* Wk = (const float*)d_in[2];
    const float* Wv = (const float*)d_in[3];
    const float* Wo = (const float*)d_in[4];
    const float* bo = (const float*)d_in[5];
    float* out = (float*)d_out;

    cudaFuncSetAttribute(gemm_qkv_tc, cudaFuncAttributeMaxDynamicSharedMemorySize, GEMM_SMEM);
    cudaFuncSetAttribute(gemm_o_tc,   cudaFuncAttributeMaxDynamicSharedMemorySize, GEMM_SMEM);

    void *pQ, *pK, *pV, *pAO;
    void *pxh, *pxl, *pqh, *pql, *pkh, *pkl, *pvh, *pvl, *poh, *pol, *paoh, *paol;
    cudaGetSymbolAddress(&pQ,  g_Q);   cudaGetSymbolAddress(&pK,  g_K);
    cudaGetSymbolAddress(&pV,  g_V);   cudaGetSymbolAddress(&pAO, g_AO);
    cudaGetSymbolAddress(&pxh, g_xh);  cudaGetSymbolAddress(&pxl, g_xl);
    cudaGetSymbolAddress(&pqh, g_wqh); cudaGetSymbolAddress(&pql, g_wql);
    cudaGetSymbolAddress(&pkh, g_wkh); cudaGetSymbolAddress(&pkl, g_wkl);
    cudaGetSymbolAddress(&pvh, g_wvh); cudaGetSymbolAddress(&pvl, g_wvl);
    cudaGetSymbolAddress(&poh, g_woh); cudaGetSymbolAddress(&pol, g_wol);
    cudaGetSymbolAddress(&paoh, g_aoh); cudaGetSymbolAddress(&paol, g_aol);

    // 1) split fp32 -> bf16 hi/lo
    split_bf16<<<(Mtot*Dd)/1024, 256>>>(x,  (__nv_bfloat16*)pxh, (__nv_bfloat16*)pxl, Mtot*Dd);
    split_bf16<<<(Dd*Dd)/1024,   256>>>(Wq, (__nv_bfloat16*)pqh, (__nv_bfloat16*)pql, Dd*Dd);
    split_bf16<<<(Dd*Dd)/1024,   256>>>(Wk, (__nv_bfloat16*)pkh, (__nv_bfloat16*)pkl, Dd*Dd);
    split_bf16<<<(Dd*Dd)/1024,   256>>>(Wv, (__nv_bfloat16*)pvh, (__nv_bfloat16*)pvl, Dd*Dd);
    split_bf16<<<(Dd*Dd)/1024,   256>>>(Wo, (__nv_bfloat16*)poh, (__nv_bfloat16*)pol, Dd*Dd);

    // 2) QKV projections (HMMA bf16x3)
    dim3 gqkv(Dd / GN, Mtot / GM, 3);
    gemm_qkv_tc<<<gqkv, 256, GEMM_SMEM>>>(
        (__nv_bfloat16*)pxh, (__nv_bfloat16*)pxl,
        (__nv_bfloat16*)pqh, (__nv_bfloat16*)pql,
        (__nv_bfloat16*)pkh, (__nv_bfloat16*)pkl,
        (__nv_bfloat16*)pvh, (__nv_bfloat16*)pvl,
        (float*)pQ, (float*)pK, (float*)pV);

    // 3) attention (scalar)
    dim3 gattn(Ss / 128, Bb * Hh);
    attn_kernel<<<gattn, 128>>>();

    // 4) split attention output, 5) output projection (+bias)
    split_bf16<<<(Mtot*Dd)/1024, 256>>>((const float*)pAO,
                                        (__nv_bfloat16*)paoh, (__nv_bfloat16*)paol, Mtot*Dd);
    dim3 gout(Dd / GN, Mtot / GM, 1);
    gemm_o_tc<<<gout, 256, GEMM_SMEM>>>(
        (__nv_bfloat16*)paoh, (__nv_bfloat16*)paol,
        (__nv_bfloat16*)poh,  (__nv_bfloat16*)pol, bo, out);
}

// round 5
// speedup vs baseline: 3.0914x; 2.4786x over previous
#include <cuda_runtime.h>
#include <cuda_bf16.h>
#include <math_constants.h>
#include <cstdint>

// Problem constants
#define Bb 2
#define Ss 2048
#define Dd 1024
#define Hh 16
#define HD 64
#define Mtot (Bb*Ss)   // 4096 rows

// ---------------------------------------------------------------------------
// Scratch (__device__ globals; allocation-free rule)
// ---------------------------------------------------------------------------
__device__ __nv_bfloat16 g_xh [Mtot*Dd], g_xl [Mtot*Dd];
__device__ __nv_bfloat16 g_wqh[Dd*Dd],   g_wql[Dd*Dd];
__device__ __nv_bfloat16 g_wkh[Dd*Dd],   g_wkl[Dd*Dd];
__device__ __nv_bfloat16 g_wvh[Dd*Dd],   g_wvl[Dd*Dd];
__device__ __nv_bfloat16 g_woh[Dd*Dd],   g_wol[Dd*Dd];
__device__ __nv_bfloat16 g_Qh [Mtot*Dd], g_Ql [Mtot*Dd];   // pre-scaled by 0.125
__device__ __nv_bfloat16 g_Kh [Mtot*Dd], g_Kl [Mtot*Dd];
__device__ __nv_bfloat16 g_Vh [Mtot*Dd], g_Vl [Mtot*Dd];
__device__ __nv_bfloat16 g_aoh[Mtot*Dd], g_aol[Mtot*Dd];

// ---------------------------------------------------------------------------
// PTX helpers (compute_103-safe: ldmatrix / mma.sync / cp.async)
// ---------------------------------------------------------------------------
__device__ __forceinline__ uint32_t smem_u32(const void* p) {
    uint32_t a;
    asm("{ .reg .u64 t; cvta.to.shared.u64 t, %1; cvt.u32.u64 %0, t; }"
        : "=r"(a) : "l"(p));
    return a;
}

__device__ __forceinline__ void ldm_x4(uint32_t& r0, uint32_t& r1,
                                       uint32_t& r2, uint32_t& r3, uint32_t addr) {
    asm volatile("ldmatrix.sync.aligned.m8n8.x4.shared.b16 {%0,%1,%2,%3}, [%4];"
                 : "=r"(r0), "=r"(r1), "=r"(r2), "=r"(r3) : "r"(addr));
}

__device__ __forceinline__ void ldm_x4_t(uint32_t& r0, uint32_t& r1,
                                         uint32_t& r2, uint32_t& r3, uint32_t addr) {
    asm volatile("ldmatrix.sync.aligned.m8n8.x4.trans.shared.b16 {%0,%1,%2,%3}, [%4];"
                 : "=r"(r0), "=r"(r1), "=r"(r2), "=r"(r3) : "r"(addr));
}

__device__ __forceinline__ void mma16816(float* c, const uint32_t* a, const uint32_t* b) {
    asm volatile(
        "mma.sync.aligned.m16n8k16.row.col.f32.bf16.bf16.f32 "
        "{%0,%1,%2,%3}, {%4,%5,%6,%7}, {%8,%9}, {%0,%1,%2,%3};"
        : "+f"(c[0]), "+f"(c[1]), "+f"(c[2]), "+f"(c[3])
        : "r"(a[0]), "r"(a[1]), "r"(a[2]), "r"(a[3]), "r"(b[0]), "r"(b[1]));
}

#define CP_ASYNC16(dst, src) \
    asm volatile("cp.async.cg.shared.global [%0], [%1], 16;" :: "r"(dst), "l"(src))
#define CP_COMMIT() asm volatile("cp.async.commit_group;" ::: "memory")
#define CP_WAIT(n)  asm volatile("cp.async.wait_group %0;" :: "n"(n) : "memory")

// pack two fp32 -> bf16x2 reg (first arg in low half = element k)
__device__ __forceinline__ uint32_t pk_bf2(float lo, float hi) {
    uint32_t r;
    asm("cvt.rn.bf16x2.f32 %0, %1, %2;" : "=r"(r) : "f"(hi), "f"(lo));
    return r;
}
__device__ __forceinline__ float bf_trunc(float x) {
    return __bfloat162float(__float2bfloat16(x));
}

// ---------------------------------------------------------------------------
// fp32 -> bf16 hi/lo split (x and weights)
// ---------------------------------------------------------------------------
__global__ __launch_bounds__(256)
void split_bf16(const float* __restrict__ src,
                __nv_bfloat16* __restrict__ hi,
                __nv_bfloat16* __restrict__ lo, int n)
{
    int i = (blockIdx.x * 256 + threadIdx.x) * 4;
    if (i >= n) return;
    float4 v = *(const float4*)(src + i);
    __nv_bfloat16 ha = __float2bfloat16(v.x);
    __nv_bfloat16 hb = __float2bfloat16(v.y);
    __nv_bfloat16 hc = __float2bfloat16(v.z);
    __nv_bfloat16 hd = __float2bfloat16(v.w);
    __nv_bfloat16 la = __float2bfloat16(v.x - __bfloat162float(ha));
    __nv_bfloat16 lb = __float2bfloat16(v.y - __bfloat162float(hb));
    __nv_bfloat16 lc = __float2bfloat16(v.z - __bfloat162float(hc));
    __nv_bfloat16 ld = __float2bfloat16(v.w - __bfloat162float(hd));
    *(__nv_bfloat162*)(hi + i)     = __halves2bfloat162(ha, hb);
    *(__nv_bfloat162*)(hi + i + 2) = __halves2bfloat162(hc, hd);
    *(__nv_bfloat162*)(lo + i)     = __halves2bfloat162(la, lb);
    *(__nv_bfloat162*)(lo + i + 2) = __halves2bfloat162(lc, ld);
}

// ---------------------------------------------------------------------------
// HMMA bf16x3 GEMM: C = (Ah+Al) @ (Bh+Bl)^T. Two epilogues:
//   SPLIT=0: fp32 + bias -> C
//   SPLIT=1: (scale*C) split into bf16 hi/lo -> Ch, Cl
// Tile 128x128x32, 8 warps, warp tile 64x32, double-buffered cp.async.
// ---------------------------------------------------------------------------
#define GM 128
#define GN 128
#define GKC 32
#define NCHUNK (Dd / GKC)        // 32
#define TILEB (128 * GKC * 2)    // 8192
#define STAGEB (4 * TILEB)       // 32KB
#define GEMM_SMEM (2 * STAGEB)   // 64KB

__device__ __forceinline__ uint32_t sw_addr(uint32_t base, int row, int unit) {
    return base + row * 64 + ((unit ^ ((row >> 1) & 3)) << 4);
}

__device__ __forceinline__ void cp_tile(uint32_t sdst, const __nv_bfloat16* __restrict__ g,
                                        int tid)
{
    #pragma unroll
    for (int i = 0; i < 2; i++) {
        int u   = tid + i * 256;
        int row = u >> 2;
        int cu  = u & 3;
        CP_ASYNC16(sw_addr(sdst, row, cu), g + (size_t)row * Dd + cu * 8);
    }
}

template<int SPLIT>
__device__ __forceinline__ void gemm_tc_body(
    const __nv_bfloat16* __restrict__ Ah, const __nv_bfloat16* __restrict__ Al,
    const __nv_bfloat16* __restrict__ Bh, const __nv_bfloat16* __restrict__ Bl,
    const float* __restrict__ bias, float* __restrict__ C,
    __nv_bfloat16* __restrict__ Ch, __nv_bfloat16* __restrict__ Cl, float scale)
{
    extern __shared__ char smem[];
    const uint32_t sb = smem_u32(smem);
    const int tid = threadIdx.x;
    const int wid = tid >> 5;
    const int lid = tid & 31;
    const int wm  = wid >> 2;
    const int wn  = wid & 3;
    const int m0  = blockIdx.y * GM;
    const int n0  = blockIdx.x * GN;

    const __nv_bfloat16* gAh = Ah + (size_t)m0 * Dd;
    const __nv_bfloat16* gAl = Al + (size_t)m0 * Dd;
    const __nv_bfloat16* gBh = Bh + (size_t)n0 * Dd;
    const __nv_bfloat16* gBl = Bl + (size_t)n0 * Dd;

    float acc[4][4][4];
    #pragma unroll
    for (int i = 0; i < 4; i++)
        #pragma unroll
        for (int j = 0; j < 4; j++)
            #pragma unroll
            for (int k = 0; k < 4; k++) acc[i][j][k] = 0.f;

    const int a_row = wm * 64 + (lid & 15);
    const int a_ku  = lid >> 4;
    const int b_row = wn * 32 + (lid & 7) + ((lid >> 4) << 3);
    const int b_ku  = (lid >> 3) & 1;

    {
        uint32_t s = sb;
        cp_tile(s,             gAh, tid);
        cp_tile(s + TILEB,     gAl, tid);
        cp_tile(s + 2*TILEB,   gBh, tid);
        cp_tile(s + 3*TILEB,   gBl, tid);
        CP_COMMIT();
    }

    for (int c = 0; c < NCHUNK; c++) {
        if (c + 1 < NCHUNK) {
            uint32_t s = sb + ((c + 1) & 1) * STAGEB;
            const int kc = (c + 1) * GKC;
            cp_tile(s,           gAh + kc, tid);
            cp_tile(s + TILEB,   gAl + kc, tid);
            cp_tile(s + 2*TILEB, gBh + kc, tid);
            cp_tile(s + 3*TILEB, gBl + kc, tid);
            CP_COMMIT();
            CP_WAIT(1);
        } else {
            CP_WAIT(0);
        }
        __syncthreads();

        const uint32_t sa_h = sb + (c & 1) * STAGEB;
        const uint32_t sa_l = sa_h + TILEB;
        const uint32_t sbh  = sa_h + 2*TILEB;
        const uint32_t sbl  = sa_h + 3*TILEB;

        #pragma unroll
        for (int ks = 0; ks < 2; ks++) {
            const int ku = ks * 2;
            uint32_t bh[8], bl[8];
            #pragma unroll
            for (int pr = 0; pr < 2; pr++) {
                ldm_x4(bh[pr*4+0], bh[pr*4+1], bh[pr*4+2], bh[pr*4+3],
                       sw_addr(sbh, b_row + pr*16, ku + b_ku));
                ldm_x4(bl[pr*4+0], bl[pr*4+1], bl[pr*4+2], bl[pr*4+3],
                       sw_addr(sbl, b_row + pr*16, ku + b_ku));
            }
            #pragma unroll
            for (int mt = 0; mt < 4; mt++) {
                uint32_t ah[4], al[4];
                ldm_x4(ah[0], ah[1], ah[2], ah[3],
                       sw_addr(sa_h, a_row + mt*16, ku + a_ku));
                ldm_x4(al[0], al[1], al[2], al[3],
                       sw_addr(sa_l, a_row + mt*16, ku + a_ku));
                #pragma unroll
                for (int nt = 0; nt < 4; nt++) {
                    mma16816(acc[mt][nt], ah, &bh[nt*2]);
                    mma16816(acc[mt][nt], al, &bh[nt*2]);
                    mma16816(acc[mt][nt], ah, &bl[nt*2]);
                }
            }
        }
        __syncthreads();
    }

    #pragma unroll
    for (int mt = 0; mt < 4; mt++) {
        const int row = m0 + wm*64 + mt*16 + (lid >> 2);
        #pragma unroll
        for (int nt = 0; nt < 4; nt++) {
            const int col = n0 + wn*32 + nt*8 + (lid & 3)*2;
            if (SPLIT) {
                #pragma unroll
                for (int half = 0; half < 2; half++) {
                    const int r = row + half * 8;
                    float va = acc[mt][nt][half*2+0] * scale;
                    float vb = acc[mt][nt][half*2+1] * scale;
                    __nv_bfloat16 ha = __float2bfloat16(va);
                    __nv_bfloat16 hb = __float2bfloat16(vb);
                    __nv_bfloat16 la = __float2bfloat16(va - __bfloat162float(ha));
                    __nv_bfloat16 lb = __float2bfloat16(vb - __bfloat162float(hb));
                    *(__nv_bfloat162*)(Ch + (size_t)r * Dd + col) = __halves2bfloat162(ha, hb);
                    *(__nv_bfloat162*)(Cl + (size_t)r * Dd + col) = __halves2bfloat162(la, lb);
                }
            } else {
                float2 v0 = make_float2(acc[mt][nt][0], acc[mt][nt][1]);
                float2 v1 = make_float2(acc[mt][nt][2], acc[mt][nt][3]);
                float2 bv = *(const float2*)(bias + col);
                v0.x += bv.x; v0.y += bv.y;
                v1.x += bv.x; v1.y += bv.y;
                *(float2*)(C + (size_t)row * Dd + col)       = v0;
                *(float2*)(C + (size_t)(row + 8) * Dd + col) = v1;
            }
        }
    }
}

__global__ __launch_bounds__(256)
void gemm_qkv_tc()
{
    const __nv_bfloat16 *Bh, *Bl; __nv_bfloat16 *Ch, *Cl; float sc;
    if (blockIdx.z == 0)      { Bh = g_wqh; Bl = g_wql; Ch = g_Qh; Cl = g_Ql; sc = 0.125f; }
    else if (blockIdx.z == 1) { Bh = g_wkh; Bl = g_wkl; Ch = g_Kh; Cl = g_Kl; sc = 1.f; }
    else                      { Bh = g_wvh; Bl = g_wvl; Ch = g_Vh; Cl = g_Vl; sc = 1.f; }
    gemm_tc_body<1>(g_xh, g_xl, Bh, Bl, nullptr, nullptr, Ch, Cl, sc);
}

__global__ __launch_bounds__(256)
void gemm_o_tc(const float* bias, float* out)
{
    gemm_tc_body<0>(g_aoh, g_aol, g_woh, g_wol, bias, out, nullptr, nullptr, 1.f);
}

// ---------------------------------------------------------------------------
// HMMA flash attention. Block = 128 q rows of one (b,h); 8 warps x 16 rows.
// KV chunks of 64 keys, double-buffered cp.async. x3 error correction on
// both QK^T and PV. Writes AO as bf16 hi/lo directly.
// Smem rows: 64 bf16 = 128B = 8 units; swizzle unit ^= row&7.
// ---------------------------------------------------------------------------
#define AQ 128
#define AKC 64
#define SQH 0
#define SQL 16384
#define SKV 32768
#define KVSTAGE 32768   // KH 0 | KL 8192 | VH 16384 | VL 24576
#define ATT_SMEM 98304

__device__ __forceinline__ uint32_t asw(uint32_t base, int row, int unit) {
    return base + row * 128 + ((unit ^ (row & 7)) << 4);
}

__device__ __forceinline__ void cp_kv(uint32_t sbase, int brow0, int h, int tid)
{
    #pragma unroll
    for (int i = 0; i < 2; i++) {
        int u = tid + i * 256;
        int row = u >> 3;
        int un = u & 7;
        size_t g = ((size_t)(brow0 + row)) * Dd + h * HD + un * 8;
        CP_ASYNC16(asw(sbase,          row, un), g_Kh + g);
        CP_ASYNC16(asw(sbase +  8192,  row, un), g_Kl + g);
        CP_ASYNC16(asw(sbase + 16384,  row, un), g_Vh + g);
        CP_ASYNC16(asw(sbase + 24576,  row, un), g_Vl + g);
    }
}

__global__ __launch_bounds__(256)
void attn_mma()
{
    extern __shared__ char smem[];
    const uint32_t sb = smem_u32(smem);
    const int tid = threadIdx.x;
    const int wid = tid >> 5;
    const int lid = tid & 31;
    const int q0  = blockIdx.x * AQ;
    const int b   = blockIdx.y >> 4;
    const int h   = blockIdx.y & 15;

    // stage Q (hi/lo): 128 rows x 8 units each
    #pragma unroll
    for (int i = 0; i < 4; i++) {
        int u = tid + i * 256;
        int row = u >> 3;
        int un = u & 7;
        size_t g = ((size_t)(b * Ss + q0 + row)) * Dd + h * HD + un * 8;
        CP_ASYNC16(asw(sb + SQH, row, un), g_Qh + g);
        CP_ASYNC16(asw(sb + SQL, row, un), g_Ql + g);
    }
    CP_COMMIT();

    // prologue KV chunk 0
    cp_kv(sb + SKV, b * Ss, h, tid);
    CP_COMMIT();

    CP_WAIT(1);   // Q resident
    __syncthreads();

    // Q fragments for this warp's 16 rows (4 k-tiles, hi/lo)
    uint32_t qh[4][4], ql[4][4];
    {
        const int r = wid * 16 + (lid & 15);
        const int ub = lid >> 4;
        #pragma unroll
        for (int ks = 0; ks < 4; ks++) {
            ldm_x4(qh[ks][0], qh[ks][1], qh[ks][2], qh[ks][3],
                   asw(sb + SQH, r, ks*2 + ub));
            ldm_x4(ql[ks][0], ql[ks][1], ql[ks][2], ql[ks][3],
                   asw(sb + SQL, r, ks*2 + ub));
        }
    }

    float o[8][4];
    #pragma unroll
    for (int i = 0; i < 8; i++)
        #pragma unroll
        for (int j = 0; j < 4; j++) o[i][j] = 0.f;
    float m0 = -CUDART_INF_F, m1 = -CUDART_INF_F, l0 = 0.f, l1 = 0.f;

    const int kb_row = (lid & 7) + ((lid >> 4) << 3);
    const int kb_ku  = (lid >> 3) & 1;
    const int v_row  = lid & 15;     // key row within 16-tile
    const int v_ub   = lid >> 4;     // +1 unit (8 d) for upper lane half

    const int NC = Ss / AKC;    // 32
    for (int c = 0; c < NC; c++) {
        if (c + 1 < NC) {
            cp_kv(sb + SKV + ((c + 1) & 1) * KVSTAGE, b * Ss + (c + 1) * AKC, h, tid);
            CP_COMMIT();
            CP_WAIT(1);
        } else {
            CP_WAIT(0);
        }
        __syncthreads();

        const uint32_t skh = sb + SKV + (c & 1) * KVSTAGE;
        const uint32_t skl = skh + 8192;
        const uint32_t svh = skh + 16384;
        const uint32_t svl = skh + 24576;

        // S = Q K^T  (x3 corrected), 16x64 per warp
        float s[8][4];
        #pragma unroll
        for (int i = 0; i < 8; i++)
            #pragma unroll
            for (int j = 0; j < 4; j++) s[i][j] = 0.f;

        #pragma unroll
        for (int ks = 0; ks < 4; ks++) {
            #pragma unroll
            for (int g = 0; g < 4; g++) {
                uint32_t kh4[4], kl4[4];
                ldm_x4(kh4[0], kh4[1], kh4[2], kh4[3],
                       asw(skh, g*16 + kb_row, ks*2 + kb_ku));
                ldm_x4(kl4[0], kl4[1], kl4[2], kl4[3],
                       asw(skl, g*16 + kb_row, ks*2 + kb_ku));
                mma16816(s[2*g],   qh[ks], &kh4[0]);
                mma16816(s[2*g],   ql[ks], &kh4[0]);
                mma16816(s[2*g],   qh[ks], &kl4[0]);
                mma16816(s[2*g+1], qh[ks], &kh4[2]);
                mma16816(s[2*g+1], ql[ks], &kh4[2]);
                mma16816(s[2*g+1], qh[ks], &kl4[2]);
            }
        }

        // online softmax (rows r and r+8 per thread)
        float rm0 = fmaxf(s[0][0], s[0][1]);
        float rm1 = fmaxf(s[0][2], s[0][3]);
        #pragma unroll
        for (int nt = 1; nt < 8; nt++) {
            rm0 = fmaxf(rm0, fmaxf(s[nt][0], s[nt][1]));
            rm1 = fmaxf(rm1, fmaxf(s[nt][2], s[nt][3]));
        }
        rm0 = fmaxf(rm0, __shfl_xor_sync(0xffffffffu, rm0, 1));
        rm0 = fmaxf(rm0, __shfl_xor_sync(0xffffffffu, rm0, 2));
        rm1 = fmaxf(rm1, __shfl_xor_sync(0xffffffffu, rm1, 1));
        rm1 = fmaxf(rm1, __shfl_xor_sync(0xffffffffu, rm1, 2));
        const float mn0 = fmaxf(m0, rm0);
        const float mn1 = fmaxf(m1, rm1);
        const float c0 = __expf(m0 - mn0);
        const float c1 = __expf(m1 - mn1);
        float sum0 = 0.f, sum1 = 0.f;
        #pragma unroll
        for (int nt = 0; nt < 8; nt++) {
            s[nt][0] = __expf(s[nt][0] - mn0); sum0 += s[nt][0];
            s[nt][1] = __expf(s[nt][1] - mn0); sum0 += s[nt][1];
            s[nt][2] = __expf(s[nt][2] - mn1); sum1 += s[nt][2];
            s[nt][3] = __expf(s[nt][3] - mn1); sum1 += s[nt][3];
            o[nt][0] *= c0; o[nt][1] *= c0;
            o[nt][2] *= c1; o[nt][3] *= c1;
        }
        sum0 += __shfl_xor_sync(0xffffffffu, sum0, 1);
        sum0 += __shfl_xor_sync(0xffffffffu, sum0, 2);
        sum1 += __shfl_xor_sync(0xffffffffu, sum1, 1);
        sum1 += __shfl_xor_sync(0xffffffffu, sum1, 2);
        l0 = l0 * c0 + sum0;
        l1 = l1 * c1 + sum1;
        m0 = mn0; m1 = mn1;

        // O += P V  (x3 corrected). P in A-frag layout per 16-key tile kt.
        // V trans-load per 16-d block db: M0={k0-7,d0-7} M1={k8-15,d0-7}
        // M2={k0-7,d8-15} M3={k8-15,d8-15}  -> (r0,r1) d-block 2*db, (r2,r3) 2*db+1
        #pragma unroll
        for (int kt = 0; kt < 4; kt++) {
            uint32_t pah[4], pal[4];
            {
                const float* t0 = s[2*kt];
                const float* t1 = s[2*kt+1];
                pah[0] = pk_bf2(t0[0], t0[1]);
                pah[1] = pk_bf2(t0[2], t0[3]);
                pah[2] = pk_bf2(t1[0], t1[1]);
                pah[3] = pk_bf2(t1[2], t1[3]);
                pal[0] = pk_bf2(t0[0]-bf_trunc(t0[0]), t0[1]-bf_trunc(t0[1]));
                pal[1] = pk_bf2(t0[2]-bf_trunc(t0[2]), t0[3]-bf_trunc(t0[3]));
                pal[2] = pk_bf2(t1[0]-bf_trunc(t1[0]), t1[1]-bf_trunc(t1[1]));
                pal[3] = pk_bf2(t1[2]-bf_trunc(t1[2]), t1[3]-bf_trunc(t1[3]));
            }
            #pragma unroll
            for (int db = 0; db < 4; db++) {   // 16 d-cols per iter
                uint32_t vh4[4], vl4[4];
                ldm_x4_t(vh4[0], vh4[1], vh4[2], vh4[3],
                         asw(svh, kt*16 + v_row, db*2 + v_ub));
                ldm_x4_t(vl4[0], vl4[1], vl4[2], vl4[3],
                         asw(svl, kt*16 + v_row, db*2 + v_ub));
                mma16816(o[2*db + 0], pah, &vh4[0]);
                mma16816(o[2*db + 0], pal, &vh4[0]);
                mma16816(o[2*db + 0], pah, &vl4[0]);
                mma16816(o[2*db + 1], pah, &vh4[2]);
                mma16816(o[2*db + 1], pal, &vh4[2]);
                mma16816(o[2*db + 1], pah, &vl4[2]);
            }
        }
        __syncthreads();
    }

    // normalize + write AO hi/lo
    const float inv0 = 1.f / l0;
    const float inv1 = 1.f / l1;
    const int gr0 = b * Ss + q0 + wid*16 + (lid >> 2);
    #pragma unroll
    for (int nt = 0; nt < 8; nt++) {
        const int col = h * HD + nt*8 + (lid & 3)*2;
        float va = o[nt][0] * inv0, vb = o[nt][1] * inv0;
        float vc = o[nt][2] * inv1, vd = o[nt][3] * inv1;
        __nv_bfloat16 ha = __float2bfloat16(va), hb = __float2bfloat16(vb);
        __nv_bfloat16 hc = __float2bfloat16(vc), hd = __float2bfloat16(vd);
        *(__nv_bfloat162*)(g_aoh + (size_t)gr0 * Dd + col) = __halves2bfloat162(ha, hb);
        *(__nv_bfloat162*)(g_aol + (size_t)gr0 * Dd + col) =
            __halves2bfloat162(__float2bfloat16(va - __bfloat162float(ha)),
                               __float2bfloat16(vb - __bfloat162float(hb)));
        *(__nv_bfloat162*)(g_aoh + (size_t)(gr0 + 8) * Dd + col) = __halves2bfloat162(hc, hd);
        *(__nv_bfloat162*)(g_aol + (size_t)(gr0 + 8) * Dd + col) =
            __halves2bfloat162(__float2bfloat16(vc - __bfloat162float(hc)),
                               __float2bfloat16(vd - __bfloat162float(hd)));
    }
}

// ---------------------------------------------------------------------------
extern "C" void kernel_launch(void* const* d_in, const int* in_sizes, int n_in,
                              void* d_out, int out_size)
{
    const float* x  = (const float*)d_in[0];
    const float* Wq = (const float*)d_in[1];
    const float* Wk = (const float*)d_in[2];
    const float* Wv = (const float*)d_in[3];
    const float* Wo = (const float*)d_in[4];
    const float* bo = (const float*)d_in[5];
    float* out = (float*)d_out;

    cudaFuncSetAttribute(gemm_qkv_tc, cudaFuncAttributeMaxDynamicSharedMemorySize, GEMM_SMEM);
    cudaFuncSetAttribute(gemm_o_tc,   cudaFuncAttributeMaxDynamicSharedMemorySize, GEMM_SMEM);
    cudaFuncSetAttribute(attn_mma,    cudaFuncAttributeMaxDynamicSharedMemorySize, ATT_SMEM);

    void *pxh, *pxl, *pqh, *pql, *pkh, *pkl, *pvh, *pvl, *poh, *pol;
    cudaGetSymbolAddress(&pxh, g_xh);  cudaGetSymbolAddress(&pxl, g_xl);
    cudaGetSymbolAddress(&pqh, g_wqh); cudaGetSymbolAddress(&pql, g_wql);
    cudaGetSymbolAddress(&pkh, g_wkh); cudaGetSymbolAddress(&pkl, g_wkl);
    cudaGetSymbolAddress(&pvh, g_wvh); cudaGetSymbolAddress(&pvl, g_wvl);
    cudaGetSymbolAddress(&poh, g_woh); cudaGetSymbolAddress(&pol, g_wol);

    // 1) split fp32 inputs -> bf16 hi/lo
    split_bf16<<<(Mtot*Dd)/1024, 256>>>(x,  (__nv_bfloat16*)pxh, (__nv_bfloat16*)pxl, Mtot*Dd);
    split_bf16<<<(Dd*Dd)/1024,   256>>>(Wq, (__nv_bfloat16*)pqh, (__nv_bfloat16*)pql, Dd*Dd);
    split_bf16<<<(Dd*Dd)/1024,   256>>>(Wk, (__nv_bfloat16*)pkh, (__nv_bfloat16*)pkl, Dd*Dd);
    split_bf16<<<(Dd*Dd)/1024,   256>>>(Wv, (__nv_bfloat16*)pvh, (__nv_bfloat16*)pvl, Dd*Dd);
    split_bf16<<<(Dd*Dd)/1024,   256>>>(Wo, (__nv_bfloat16*)poh, (__nv_bfloat16*)pol, Dd*Dd);

    // 2) QKV projections -> bf16 hi/lo (Q pre-scaled by 1/sqrt(HD))
    dim3 gqkv(Dd / GN, Mtot / GM, 3);
    gemm_qkv_tc<<<gqkv, 256, GEMM_SMEM>>>();

    // 3) HMMA flash attention -> AO hi/lo
    dim3 gattn(Ss / AQ, Bb * Hh);
    attn_mma<<<gattn, 256, ATT_SMEM>>>();

    // 4) output projection (+bias) -> fp32 out
    dim3 gout(Dd / GN, Mtot / GM, 1);
    gemm_o_tc<<<gout, 256, GEMM_SMEM>>>(bo, out);
}